// round 1
// baseline (speedup 1.0000x reference)
#include <cuda_runtime.h>
#include <cuda_bf16.h>

#define BT    256
#define LTOK  197
#define CDIM  768
#define CADIM 384
#define NB    32
#define NT    8
#define NH    14
#define NW    14
#define MDIM  (BT*196)   /* 50176 */

// ---------------- scratch (global __device__ arrays; no allocation) ----------------
__device__ __nv_bfloat16 g_h1[(size_t)MDIM * CADIM];   // fc1 output (bf16)
__device__ __nv_bfloat16 g_hc[(size_t)MDIM * CADIM];   // conv output (bf16)
__device__ __nv_bfloat16 g_w1b[CADIM * CDIM];          // W1 bf16 [CA][C]
__device__ __nv_bfloat16 g_w2b[CDIM * CADIM];          // W2 bf16 [C][CA]
__device__ float         g_cwT[27 * CADIM];            // conv weights transposed [tap][ca]

// ---------------- small helpers ----------------
__device__ __forceinline__ unsigned pack2(float a, float b) {
    __nv_bfloat162 t = __floats2bfloat162_rn(a, b);
    return *reinterpret_cast<unsigned*>(&t);
}
__device__ __forceinline__ void ldsm4(unsigned& r0, unsigned& r1, unsigned& r2, unsigned& r3, unsigned addr) {
    asm volatile("ldmatrix.sync.aligned.m8n8.x4.shared.b16 {%0,%1,%2,%3}, [%4];\n"
                 : "=r"(r0), "=r"(r1), "=r"(r2), "=r"(r3) : "r"(addr));
}
__device__ __forceinline__ void ldsm2(unsigned& r0, unsigned& r1, unsigned addr) {
    asm volatile("ldmatrix.sync.aligned.m8n8.x2.shared.b16 {%0,%1}, [%2];\n"
                 : "=r"(r0), "=r"(r1) : "r"(addr));
}
__device__ __forceinline__ void mma16816(float* c, const unsigned* a, const unsigned* b) {
    asm volatile(
        "mma.sync.aligned.m16n8k16.row.col.f32.bf16.bf16.f32 "
        "{%0,%1,%2,%3}, {%4,%5,%6,%7}, {%8,%9}, {%0,%1,%2,%3};\n"
        : "+f"(c[0]), "+f"(c[1]), "+f"(c[2]), "+f"(c[3])
        : "r"(a[0]), "r"(a[1]), "r"(a[2]), "r"(a[3]), "r"(b[0]), "r"(b[1]));
}

// ---------------- weight conversion / transpose ----------------
__global__ void convert_weights(const float* __restrict__ W1, const float* __restrict__ W2,
                                const float* __restrict__ cw) {
    int i = blockIdx.x * 256 + threadIdx.x;
    if (i < CADIM * CDIM) {
        g_w1b[i] = __float2bfloat16(W1[i]);
        g_w2b[i] = __float2bfloat16(W2[i]);
    }
    if (i < 27 * CADIM) {
        int j = i / CADIM, ca = i % CADIM;
        g_cwT[i] = cw[ca * 27 + j];
    }
}

// ---------------- GEMM (bf16 mma.sync, fp32 accum) ----------------
// MODE 0: h1[M,384] = gather(x)[M,768] @ W1^T + b1          (A fp32, inline convert)
// MODE 1: out[gather] = x + hc[M,384] @ W2^T + b2           (A bf16)
template <int MODE>
__global__ __launch_bounds__(256) void gemm_kernel(
    const float* __restrict__ x, const float* __restrict__ bias, float* __restrict__ out)
{
    constexpr int K  = (MODE == 0) ? CDIM : CADIM;
    constexpr int N  = (MODE == 0) ? CADIM : CDIM;
    constexpr int KT = K / 32;

    __shared__ __nv_bfloat16 As[2][128][40];
    __shared__ __nv_bfloat16 Bs[2][128][40];

    const int tid = threadIdx.x;
    const int bn = blockIdx.x, bm = blockIdx.y;
    const int warp = tid >> 5, lane = tid & 31;
    const int wm = warp >> 2, wn = warp & 3;

    const int ldr = tid >> 2;            // 0..63
    const int ldc = (tid & 3) * 8;       // 0,8,16,24

    const float* arow0_f = nullptr; const float* arow1_f = nullptr;
    const __nv_bfloat16* arow0_h = nullptr; const __nv_bfloat16* arow1_h = nullptr;
    {
        int m0 = bm * 128 + ldr;
        int m1 = m0 + 64;
        if (MODE == 0) {
            int bt0 = m0 / 196, l0 = m0 - bt0 * 196;
            int bt1 = m1 / 196, l1 = m1 - bt1 * 196;
            arow0_f = x + (size_t)(bt0 * LTOK + 1 + l0) * CDIM + ldc;
            arow1_f = x + (size_t)(bt1 * LTOK + 1 + l1) * CDIM + ldc;
        } else {
            arow0_h = g_hc + (size_t)m0 * K + ldc;
            arow1_h = g_hc + (size_t)m1 * K + ldc;
        }
    }
    const __nv_bfloat16* Bw = (MODE == 0) ? g_w1b : g_w2b;
    const __nv_bfloat16* brow0 = Bw + (size_t)(bn * 128 + ldr) * K + ldc;
    const __nv_bfloat16* brow1 = brow0 + (size_t)64 * K;

    float acc[4][4][4];
    #pragma unroll
    for (int i = 0; i < 4; i++)
        #pragma unroll
        for (int j = 0; j < 4; j++)
            #pragma unroll
            for (int q = 0; q < 4; q++) acc[i][j][q] = 0.f;

    uint4 ra0, ra1, rb0, rb1;

    auto LDG = [&](int kt) {
        int k0 = kt * 32;
        if (MODE == 0) {
            float4 v0 = *reinterpret_cast<const float4*>(arow0_f + k0);
            float4 v1 = *reinterpret_cast<const float4*>(arow0_f + k0 + 4);
            ra0 = make_uint4(pack2(v0.x, v0.y), pack2(v0.z, v0.w), pack2(v1.x, v1.y), pack2(v1.z, v1.w));
            float4 w0 = *reinterpret_cast<const float4*>(arow1_f + k0);
            float4 w1 = *reinterpret_cast<const float4*>(arow1_f + k0 + 4);
            ra1 = make_uint4(pack2(w0.x, w0.y), pack2(w0.z, w0.w), pack2(w1.x, w1.y), pack2(w1.z, w1.w));
        } else {
            ra0 = *reinterpret_cast<const uint4*>(arow0_h + k0);
            ra1 = *reinterpret_cast<const uint4*>(arow1_h + k0);
        }
        rb0 = *reinterpret_cast<const uint4*>(brow0 + k0);
        rb1 = *reinterpret_cast<const uint4*>(brow1 + k0);
    };
    auto STS = [&](int buf) {
        *reinterpret_cast<uint4*>(&As[buf][ldr][ldc])      = ra0;
        *reinterpret_cast<uint4*>(&As[buf][ldr + 64][ldc]) = ra1;
        *reinterpret_cast<uint4*>(&Bs[buf][ldr][ldc])      = rb0;
        *reinterpret_cast<uint4*>(&Bs[buf][ldr + 64][ldc]) = rb1;
    };

    LDG(0); STS(0); __syncthreads();

    unsigned aBase = (unsigned)__cvta_generic_to_shared(&As[0][0][0]);
    unsigned bBase = (unsigned)__cvta_generic_to_shared(&Bs[0][0][0]);
    const int a_row  = wm * 64 + (lane & 15);
    const int a_coff = (lane >> 4) * 8;
    const int b_row  = wn * 32 + (lane & 7);
    const int b_coff = ((lane >> 3) & 1) * 8;

    for (int kt = 0; kt < KT; ++kt) {
        int cur = kt & 1;
        if (kt + 1 < KT) LDG(kt + 1);
        unsigned aoff = aBase + cur * (128 * 40 * 2);
        unsigned boff = bBase + cur * (128 * 40 * 2);
        #pragma unroll
        for (int ks = 0; ks < 2; ++ks) {
            unsigned afr[4][4], bfr[4][2];
            #pragma unroll
            for (int mf = 0; mf < 4; ++mf) {
                unsigned addr = aoff + (unsigned)((a_row + mf * 16) * 80 + (ks * 16 + a_coff) * 2);
                ldsm4(afr[mf][0], afr[mf][1], afr[mf][2], afr[mf][3], addr);
            }
            #pragma unroll
            for (int nf = 0; nf < 4; ++nf) {
                unsigned addr = boff + (unsigned)((b_row + nf * 8) * 80 + (ks * 16 + b_coff) * 2);
                ldsm2(bfr[nf][0], bfr[nf][1], addr);
            }
            #pragma unroll
            for (int mf = 0; mf < 4; ++mf)
                #pragma unroll
                for (int nf = 0; nf < 4; ++nf)
                    mma16816(acc[mf][nf], afr[mf], bfr[nf]);
        }
        if (kt + 1 < KT) { STS((kt + 1) & 1); __syncthreads(); }
    }

    // epilogue
    #pragma unroll
    for (int mf = 0; mf < 4; ++mf) {
        int mrow0 = bm * 128 + wm * 64 + mf * 16 + (lane >> 2);
        #pragma unroll
        for (int rr = 0; rr < 2; ++rr) {
            int m = mrow0 + rr * 8;
            if (MODE == 0) {
                __nv_bfloat16* dst = g_h1 + (size_t)m * N;
                #pragma unroll
                for (int nf = 0; nf < 4; ++nf) {
                    int n = bn * 128 + wn * 32 + nf * 8 + (lane & 3) * 2;
                    float v0 = acc[mf][nf][rr * 2 + 0] + bias[n];
                    float v1 = acc[mf][nf][rr * 2 + 1] + bias[n + 1];
                    __nv_bfloat162 t = __floats2bfloat162_rn(v0, v1);
                    *reinterpret_cast<__nv_bfloat162*>(dst + n) = t;
                }
            } else {
                int bt = m / 196, l = m - bt * 196;
                size_t base = (size_t)(bt * LTOK + 1 + l) * CDIM;
                #pragma unroll
                for (int nf = 0; nf < 4; ++nf) {
                    int n = bn * 128 + wn * 32 + nf * 8 + (lane & 3) * 2;
                    float2 xv = *reinterpret_cast<const float2*>(x + base + n);
                    float2 o;
                    o.x = acc[mf][nf][rr * 2 + 0] + bias[n]     + xv.x;
                    o.y = acc[mf][nf][rr * 2 + 1] + bias[n + 1] + xv.y;
                    *reinterpret_cast<float2*>(out + base + n) = o;
                }
            }
        }
    }
}

// ---------------- depthwise 3x3x3 conv over (T,H,W) ----------------
__global__ void conv_kernel(const float* __restrict__ cb) {
    int idx = blockIdx.x * 256 + threadIdx.x;
    if (idx >= (int)((size_t)MDIM * CADIM)) return;
    int ca = idx % CADIM;
    int s  = idx / CADIM;
    int w  = s % NW; s /= NW;
    int h  = s % NH; s /= NH;
    int t  = s % NT;
    int b  = s / NT;

    float acc = cb[ca];
    #pragma unroll
    for (int dt = -1; dt <= 1; ++dt) {
        int tt = t + dt;
        if (tt < 0 || tt >= NT) continue;
        #pragma unroll
        for (int dh = -1; dh <= 1; ++dh) {
            int hh = h + dh;
            if (hh < 0 || hh >= NH) continue;
            #pragma unroll
            for (int dw = -1; dw <= 1; ++dw) {
                int ww = w + dw;
                if (ww < 0 || ww >= NW) continue;
                int j = (dt + 1) * 9 + (dh + 1) * 3 + (dw + 1);
                float v = __bfloat162float(
                    g_h1[((size_t)((b * NT + tt) * 196) + (hh * NW + ww)) * CADIM + ca]);
                acc += v * g_cwT[j * CADIM + ca];
            }
        }
    }
    g_hc[idx] = __float2bfloat16(acc);
}

// ---------------- CLS token passthrough ----------------
__global__ void cls_copy(const float* __restrict__ x, float* __restrict__ out) {
    int i = blockIdx.x * 256 + threadIdx.x;
    if (i < BT * CDIM) {
        int bt = i / CDIM, c = i % CDIM;
        size_t off = (size_t)bt * LTOK * CDIM + c;
        out[off] = x[off];
    }
}

// ---------------- launch ----------------
extern "C" void kernel_launch(void* const* d_in, const int* in_sizes, int n_in,
                              void* d_out, int out_size) {
    const float* x      = (const float*)d_in[0];
    const float* W1     = (const float*)d_in[1];
    const float* b1     = (const float*)d_in[2];
    const float* conv_w = (const float*)d_in[3];
    const float* conv_b = (const float*)d_in[4];
    const float* W2     = (const float*)d_in[5];
    const float* b2     = (const float*)d_in[6];
    float* out = (float*)d_out;

    convert_weights<<<(CADIM * CDIM + 255) / 256, 256>>>(W1, W2, conv_w);
    gemm_kernel<0><<<dim3(CADIM / 128, MDIM / 128), 256>>>(x, b1, nullptr);
    conv_kernel<<<(int)(((size_t)MDIM * CADIM + 255) / 256), 256>>>(conv_b);
    gemm_kernel<1><<<dim3(CDIM / 128, MDIM / 128), 256>>>(x, b2, out);
    cls_copy<<<(BT * CDIM + 255) / 256, 256>>>(x, out);
}

// round 11
// speedup vs baseline: 1.8077x; 1.8077x over previous
#include <cuda_runtime.h>
#include <cuda_bf16.h>
#include <cstdint>

#define BT    256
#define LTOK  197
#define CDIM  768
#define CADIM 384
#define NT    8
#define NH    14
#define NW    14
#define MDIM  (BT*196)   /* 50176 */

// ---------------- scratch ----------------
__device__ __align__(256) __nv_bfloat16 g_h1[(size_t)MDIM * CADIM];
__device__ __align__(256) __nv_bfloat16 g_hc[(size_t)MDIM * CADIM];
__device__ __align__(256) __nv_bfloat16 g_w1b[CADIM * CDIM];
__device__ __align__(256) __nv_bfloat16 g_w2b[CDIM * CADIM];
__device__ __align__(256) float         g_cwT[27 * CADIM];

// ---------------- helpers ----------------
__device__ __forceinline__ unsigned sm32(const void* p) {
    unsigned a;
    asm("{.reg .u64 t; cvta.to.shared.u64 t, %1; cvt.u32.u64 %0, t;}" : "=r"(a) : "l"(p));
    return a;
}
__device__ __forceinline__ unsigned pack2(float a, float b) {
    __nv_bfloat162 t = __floats2bfloat162_rn(a, b);
    return *reinterpret_cast<unsigned*>(&t);
}
__device__ __forceinline__ void ldsm4(unsigned& r0, unsigned& r1, unsigned& r2, unsigned& r3, unsigned addr) {
    asm volatile("ldmatrix.sync.aligned.m8n8.x4.shared.b16 {%0,%1,%2,%3}, [%4];\n"
                 : "=r"(r0), "=r"(r1), "=r"(r2), "=r"(r3) : "r"(addr));
}
__device__ __forceinline__ void ldsm2(unsigned& r0, unsigned& r1, unsigned addr) {
    asm volatile("ldmatrix.sync.aligned.m8n8.x2.shared.b16 {%0,%1}, [%2];\n"
                 : "=r"(r0), "=r"(r1) : "r"(addr));
}
__device__ __forceinline__ void mma16816(float* c, const unsigned* a, const unsigned* b) {
    asm volatile(
        "mma.sync.aligned.m16n8k16.row.col.f32.bf16.bf16.f32 "
        "{%0,%1,%2,%3}, {%4,%5,%6,%7}, {%8,%9}, {%0,%1,%2,%3};\n"
        : "+f"(c[0]), "+f"(c[1]), "+f"(c[2]), "+f"(c[3])
        : "r"(a[0]), "r"(a[1]), "r"(a[2]), "r"(a[3]), "r"(b[0]), "r"(b[1]));
}

#define CP_ASYNC16(sa, ga) \
    asm volatile("cp.async.cg.shared.global [%0], [%1], 16;" :: "r"(sa), "l"(ga) : "memory")
#define CP_COMMIT() asm volatile("cp.async.commit_group;" ::: "memory")
#define CP_WAIT1()  asm volatile("cp.async.wait_group 1;" ::: "memory")
#define CP_WAIT0()  asm volatile("cp.async.wait_group 0;" ::: "memory")

// ---------------- weight conversion ----------------
__global__ void convert_weights(const float* __restrict__ W1, const float* __restrict__ W2,
                                const float* __restrict__ cw) {
    int i = blockIdx.x * 256 + threadIdx.x;
    if (i < CADIM * CDIM) {
        g_w1b[i] = __float2bfloat16(W1[i]);
        g_w2b[i] = __float2bfloat16(W2[i]);
    }
    if (i < 27 * CADIM) {
        int j = i / CADIM, ca = i % CADIM;
        g_cwT[i] = cw[ca * 27 + j];
    }
}

// ---------------- GEMM: mma.sync bf16, CTA 128x128, 4 warps @ 64x64, cp.async pipeline ----
// MODE 0: h1 = gather(x) @ W1^T + b1   (A fp32 inline-convert)
// MODE 1: out = x + hc @ W2^T + b2
template <int MODE>
__global__ __launch_bounds__(128, 2) void gemm_mma(
    const float* __restrict__ x, const float* __restrict__ bias, float* __restrict__ out)
{
    constexpr int K  = (MODE == 0) ? CDIM : CADIM;
    constexpr int KT = K / 32;

    __shared__ __align__(16) __nv_bfloat16 As[2][128][40];
    __shared__ __align__(16) __nv_bfloat16 Bs[2][128][40];

    const int tid  = threadIdx.x;
    const int warp = tid >> 5, lane = tid & 31;
    const int wm = warp >> 1, wn = warp & 1;
    const int bn = blockIdx.x, bm = blockIdx.y;

    const __nv_bfloat16* Bw = (MODE == 0) ? g_w1b : g_w2b;

    // loader: each thread owns 4 rows (r0 + t*32), one 16B chunk per row (col group jj)
    const int jj = tid & 3;
    const int r0 = tid >> 2;

    const float* aF[4];
    const __nv_bfloat16* aH[4];
    const __nv_bfloat16* bP[4];
    #pragma unroll
    for (int t = 0; t < 4; ++t) {
        int row = r0 + t * 32;
        int m = bm * 128 + row;
        if (MODE == 0) {
            int bt = m / 196, l = m - bt * 196;
            aF[t] = x + (size_t)(bt * LTOK + 1 + l) * CDIM + jj * 8;
            aH[t] = nullptr;
        } else {
            aF[t] = nullptr;
            aH[t] = g_hc + (size_t)m * K + jj * 8;
        }
        bP[t] = Bw + (size_t)(bn * 128 + row) * K + jj * 8;
    }

    auto issue = [&](int buf, int kb) {
        #pragma unroll
        for (int t = 0; t < 4; ++t) {
            int row = r0 + t * 32;
            unsigned da = sm32(&As[buf][row][jj * 8]);
            if (MODE == 0) {
                const float* p = aF[t] + kb * 32;
                float4 v0 = *(const float4*)p;
                float4 v1 = *(const float4*)(p + 4);
                unsigned p0 = pack2(v0.x, v0.y), p1 = pack2(v0.z, v0.w);
                unsigned p2 = pack2(v1.x, v1.y), p3 = pack2(v1.z, v1.w);
                asm volatile("st.shared.v4.b32 [%0], {%1,%2,%3,%4};"
                             :: "r"(da), "r"(p0), "r"(p1), "r"(p2), "r"(p3) : "memory");
            } else {
                CP_ASYNC16(da, aH[t] + kb * 32);
            }
            unsigned db = sm32(&Bs[buf][row][jj * 8]);
            CP_ASYNC16(db, bP[t] + kb * 32);
        }
        CP_COMMIT();
    };

    float acc[4][8][4];
    #pragma unroll
    for (int i = 0; i < 4; ++i)
        #pragma unroll
        for (int j = 0; j < 8; ++j)
            #pragma unroll
            for (int q = 0; q < 4; ++q) acc[i][j][q] = 0.f;

    issue(0, 0);
    issue(1, 1);   // KT >= 12 always

    const int a_row  = wm * 64 + (lane & 15);
    const int a_coff = (lane >> 4) * 8;
    const int b_row  = wn * 64 + (lane & 7);
    const int b_coff = ((lane >> 3) & 1) * 8;
    const unsigned abase = sm32(&As[0][0][0]);
    const unsigned bbase = sm32(&Bs[0][0][0]);

    for (int kt = 0; kt < KT; ++kt) {
        int cur = kt & 1;
        if (kt + 1 < KT) { CP_WAIT1(); } else { CP_WAIT0(); }
        __syncthreads();
        unsigned aoff = abase + cur * (128 * 40 * 2);
        unsigned boff = bbase + cur * (128 * 40 * 2);
        #pragma unroll
        for (int ks = 0; ks < 2; ++ks) {
            unsigned afr[4][4], bfr[8][2];
            #pragma unroll
            for (int mf = 0; mf < 4; ++mf)
                ldsm4(afr[mf][0], afr[mf][1], afr[mf][2], afr[mf][3],
                      aoff + (unsigned)((a_row + mf * 16) * 80 + (ks * 16 + a_coff) * 2));
            #pragma unroll
            for (int nf = 0; nf < 8; ++nf)
                ldsm2(bfr[nf][0], bfr[nf][1],
                      boff + (unsigned)((b_row + nf * 8) * 80 + (ks * 16 + b_coff) * 2));
            #pragma unroll
            for (int mf = 0; mf < 4; ++mf)
                #pragma unroll
                for (int nf = 0; nf < 8; ++nf)
                    mma16816(acc[mf][nf], afr[mf], bfr[nf]);
        }
        __syncthreads();
        if (kt + 2 < KT) issue(cur, kt + 2);
    }

    // ---- epilogue ----
    #pragma unroll
    for (int mf = 0; mf < 4; ++mf) {
        #pragma unroll
        for (int rr = 0; rr < 2; ++rr) {
            int m = bm * 128 + wm * 64 + mf * 16 + (lane >> 2) + rr * 8;
            if (MODE == 0) {
                __nv_bfloat16* dst = g_h1 + (size_t)m * CADIM + bn * 128;
                #pragma unroll
                for (int nf = 0; nf < 8; ++nf) {
                    int n = wn * 64 + nf * 8 + (lane & 3) * 2;
                    float v0 = acc[mf][nf][rr * 2 + 0] + bias[bn * 128 + n];
                    float v1 = acc[mf][nf][rr * 2 + 1] + bias[bn * 128 + n + 1];
                    __nv_bfloat162 tv = __floats2bfloat162_rn(v0, v1);
                    *reinterpret_cast<__nv_bfloat162*>(dst + n) = tv;
                }
            } else {
                int bt = m / 196, l = m - bt * 196;
                size_t base = (size_t)(bt * LTOK + 1 + l) * CDIM + bn * 128;
                #pragma unroll
                for (int nf = 0; nf < 8; ++nf) {
                    int n = wn * 64 + nf * 8 + (lane & 3) * 2;
                    float2 xv = *(const float2*)(x + base + n);
                    float2 o;
                    o.x = acc[mf][nf][rr * 2 + 0] + bias[bn * 128 + n]     + xv.x;
                    o.y = acc[mf][nf][rr * 2 + 1] + bias[bn * 128 + n + 1] + xv.y;
                    *(float2*)(out + base + n) = o;
                }
            }
        }
    }
}

// ---------------- depthwise 3x3x3 conv: 8 channels/thread ----------------
__global__ void conv_kernel(const float* __restrict__ cb) {
    int i = blockIdx.x * 256 + threadIdx.x;
    if (i >= MDIM * (CADIM / 8)) return;
    int g  = i % (CADIM / 8);
    int s  = i / (CADIM / 8);
    int ca = g * 8;
    int w  = s % NW;
    int r  = s / NW;
    int h  = r % NH; r /= NH;
    int t  = r % NT;
    int b  = r / NT;

    float acc[8];
    {
        float4 bz0 = *(const float4*)(cb + ca);
        float4 bz1 = *(const float4*)(cb + ca + 4);
        acc[0] = bz0.x; acc[1] = bz0.y; acc[2] = bz0.z; acc[3] = bz0.w;
        acc[4] = bz1.x; acc[5] = bz1.y; acc[6] = bz1.z; acc[7] = bz1.w;
    }

    #pragma unroll
    for (int dt = -1; dt <= 1; ++dt) {
        int tt = t + dt;
        if (tt < 0 || tt >= NT) continue;
        #pragma unroll
        for (int dh = -1; dh <= 1; ++dh) {
            int hh = h + dh;
            if (hh < 0 || hh >= NH) continue;
            #pragma unroll
            for (int dw = -1; dw <= 1; ++dw) {
                int ww = w + dw;
                if (ww < 0 || ww >= NW) continue;
                int j = (dt + 1) * 9 + (dh + 1) * 3 + (dw + 1);
                uint4 v = *(const uint4*)(g_h1 +
                    ((size_t)((b * NT + tt) * 196) + (hh * NW + ww)) * CADIM + ca);
                float4 w0 = *(const float4*)(g_cwT + j * CADIM + ca);
                float4 w1 = *(const float4*)(g_cwT + j * CADIM + ca + 4);
                float2 f0 = __bfloat1622float2(*reinterpret_cast<__nv_bfloat162*>(&v.x));
                float2 f1 = __bfloat1622float2(*reinterpret_cast<__nv_bfloat162*>(&v.y));
                float2 f2 = __bfloat1622float2(*reinterpret_cast<__nv_bfloat162*>(&v.z));
                float2 f3 = __bfloat1622float2(*reinterpret_cast<__nv_bfloat162*>(&v.w));
                acc[0] = fmaf(f0.x, w0.x, acc[0]);
                acc[1] = fmaf(f0.y, w0.y, acc[1]);
                acc[2] = fmaf(f1.x, w0.z, acc[2]);
                acc[3] = fmaf(f1.y, w0.w, acc[3]);
                acc[4] = fmaf(f2.x, w1.x, acc[4]);
                acc[5] = fmaf(f2.y, w1.y, acc[5]);
                acc[6] = fmaf(f3.x, w1.z, acc[6]);
                acc[7] = fmaf(f3.y, w1.w, acc[7]);
            }
        }
    }
    uint4 o;
    o.x = pack2(acc[0], acc[1]);
    o.y = pack2(acc[2], acc[3]);
    o.z = pack2(acc[4], acc[5]);
    o.w = pack2(acc[6], acc[7]);
    *(uint4*)(g_hc + (size_t)s * CADIM + ca) = o;
}

// ---------------- CLS passthrough ----------------
__global__ void cls_copy(const float* __restrict__ x, float* __restrict__ out) {
    int i = blockIdx.x * 256 + threadIdx.x;
    if (i < BT * CDIM) {
        int bt = i / CDIM, c = i % CDIM;
        size_t off = (size_t)bt * LTOK * CDIM + c;
        out[off] = x[off];
    }
}

// ---------------- launch ----------------
extern "C" void kernel_launch(void* const* d_in, const int* in_sizes, int n_in,
                              void* d_out, int out_size) {
    const float* x      = (const float*)d_in[0];
    const float* W1     = (const float*)d_in[1];
    const float* b1     = (const float*)d_in[2];
    const float* conv_w = (const float*)d_in[3];
    const float* conv_b = (const float*)d_in[4];
    const float* W2     = (const float*)d_in[5];
    const float* b2     = (const float*)d_in[6];
    float* out = (float*)d_out;

    convert_weights<<<(CADIM * CDIM + 255) / 256, 256>>>(W1, W2, conv_w);
    gemm_mma<0><<<dim3(CADIM / 128, MDIM / 128), 128>>>(x, b1, nullptr);
    conv_kernel<<<(MDIM * (CADIM / 8) + 255) / 256, 256>>>(conv_b);
    gemm_mma<1><<<dim3(CDIM / 128, MDIM / 128), 128>>>(x, b2, out);
    cls_copy<<<(BT * CDIM + 255) / 256, 256>>>(x, out);
}

// round 14
// speedup vs baseline: 1.8515x; 1.0242x over previous
#include <cuda_runtime.h>
#include <cuda_bf16.h>
#include <cstdint>

#define BT    256
#define LTOK  197
#define CDIM  768
#define CADIM 384
#define NT    8
#define NH    14
#define NW    14
#define MDIM  (BT*196)   /* 50176 */

// ---------------- scratch ----------------
__device__ __align__(256) __nv_bfloat16 g_xb[(size_t)MDIM * CDIM];    // x bf16, CLS removed
__device__ __align__(256) __nv_bfloat16 g_h1[(size_t)MDIM * CADIM];
__device__ __align__(256) __nv_bfloat16 g_hc[(size_t)MDIM * CADIM];
__device__ __align__(256) __nv_bfloat16 g_w1b[CADIM * CDIM];
__device__ __align__(256) __nv_bfloat16 g_w2b[CDIM * CADIM];
__device__ __align__(256) float         g_cwT[27 * CADIM];

// ---------------- helpers ----------------
__device__ __forceinline__ unsigned sm32(const void* p) {
    unsigned a;
    asm("{.reg .u64 t; cvta.to.shared.u64 t, %1; cvt.u32.u64 %0, t;}" : "=r"(a) : "l"(p));
    return a;
}
__device__ __forceinline__ unsigned pack2(float a, float b) {
    __nv_bfloat162 t = __floats2bfloat162_rn(a, b);
    return *reinterpret_cast<unsigned*>(&t);
}
__device__ __forceinline__ void ldsm4(unsigned& r0, unsigned& r1, unsigned& r2, unsigned& r3, unsigned addr) {
    asm volatile("ldmatrix.sync.aligned.m8n8.x4.shared.b16 {%0,%1,%2,%3}, [%4];\n"
                 : "=r"(r0), "=r"(r1), "=r"(r2), "=r"(r3) : "r"(addr));
}
__device__ __forceinline__ void ldsm2(unsigned& r0, unsigned& r1, unsigned addr) {
    asm volatile("ldmatrix.sync.aligned.m8n8.x2.shared.b16 {%0,%1}, [%2];\n"
                 : "=r"(r0), "=r"(r1) : "r"(addr));
}
__device__ __forceinline__ void mma16816(float* c, const unsigned* a, const unsigned* b) {
    asm volatile(
        "mma.sync.aligned.m16n8k16.row.col.f32.bf16.bf16.f32 "
        "{%0,%1,%2,%3}, {%4,%5,%6,%7}, {%8,%9}, {%0,%1,%2,%3};\n"
        : "+f"(c[0]), "+f"(c[1]), "+f"(c[2]), "+f"(c[3])
        : "r"(a[0]), "r"(a[1]), "r"(a[2]), "r"(a[3]), "r"(b[0]), "r"(b[1]));
}

#define CP_ASYNC16(sa, ga) \
    asm volatile("cp.async.cg.shared.global [%0], [%1], 16;" :: "r"(sa), "l"(ga) : "memory")
#define CP_COMMIT() asm volatile("cp.async.commit_group;" ::: "memory")
#define CP_WAIT1()  asm volatile("cp.async.wait_group 1;" ::: "memory")
#define CP_WAIT0()  asm volatile("cp.async.wait_group 0;" ::: "memory")

// ---------------- weight conversion ----------------
__global__ void convert_weights(const float* __restrict__ W1, const float* __restrict__ W2,
                                const float* __restrict__ cw) {
    int i = blockIdx.x * 256 + threadIdx.x;
    if (i < CADIM * CDIM) {
        g_w1b[i] = __float2bfloat16(W1[i]);
        g_w2b[i] = __float2bfloat16(W2[i]);
    }
    if (i < 27 * CADIM) {
        int j = i / CADIM, ca = i % CADIM;
        g_cwT[i] = cw[ca * 27 + j];
    }
}

// ---------------- x fp32 -> bf16 compact (CLS removed) + CLS passthrough ----------------
__global__ void convert_x_cls(const float* __restrict__ x, float* __restrict__ out) {
    int i = blockIdx.x * 256 + threadIdx.x;
    // convert: 8 elems per thread
    if (i < MDIM * (CDIM / 8)) {
        int m = i / (CDIM / 8);
        int part = i - m * (CDIM / 8);
        int bt = m / 196, l = m - bt * 196;
        const float* src = x + (size_t)(bt * LTOK + 1 + l) * CDIM + part * 8;
        float4 v0 = *(const float4*)src;
        float4 v1 = *(const float4*)(src + 4);
        uint4 o = make_uint4(pack2(v0.x, v0.y), pack2(v0.z, v0.w),
                             pack2(v1.x, v1.y), pack2(v1.z, v1.w));
        *(uint4*)(g_xb + (size_t)m * CDIM + part * 8) = o;
    }
    // CLS copy: float4 per thread
    if (i < BT * (CDIM / 4)) {
        int bt = i / (CDIM / 4);
        int c  = (i - bt * (CDIM / 4)) * 4;
        size_t off = (size_t)bt * LTOK * CDIM + c;
        *(float4*)(out + off) = *(const float4*)(x + off);
    }
}

// ---------------- GEMM: mma.sync bf16, CTA 128x128, 4 warps @ 64x64, 3-stage cp.async ----
// MODE 0: h1 = g_xb @ W1^T + b1      (K=768)
// MODE 1: out = x + g_hc @ W2^T + b2 (K=384)
#define TILE_B  10240                 /* 128*40*2 bytes per stage per operand */
#define SMEM_SZ (6 * TILE_B)          /* 3 stages x (A,B) = 61440 */

template <int MODE>
__global__ __launch_bounds__(128, 2) void gemm_mma(
    const float* __restrict__ x, const float* __restrict__ bias, float* __restrict__ out)
{
    constexpr int K  = (MODE == 0) ? CDIM : CADIM;
    constexpr int KT = K / 32;

    extern __shared__ char smem[];
    const unsigned sbase = sm32(smem);

    const int tid  = threadIdx.x;
    const int warp = tid >> 5, lane = tid & 31;
    const int wm = warp >> 1, wn = warp & 1;
    const int bn = blockIdx.x, bm = blockIdx.y;

    const __nv_bfloat16* Asrc = (MODE == 0) ? g_xb : g_hc;
    const __nv_bfloat16* Bw   = (MODE == 0) ? g_w1b : g_w2b;

    // loader: thread owns 4 rows (r0 + t*32), one 16B chunk (col group jj) per row
    const int jj = tid & 3;
    const int r0 = tid >> 2;

    const __nv_bfloat16* aP[4];
    const __nv_bfloat16* bP[4];
    #pragma unroll
    for (int t = 0; t < 4; ++t) {
        int row = r0 + t * 32;
        aP[t] = Asrc + (size_t)(bm * 128 + row) * K + jj * 8;
        bP[t] = Bw   + (size_t)(bn * 128 + row) * K + jj * 8;
    }

    auto issue = [&](int buf, int kb) {
        unsigned abuf = sbase + buf * TILE_B;
        unsigned bbuf = sbase + 3 * TILE_B + buf * TILE_B;
        #pragma unroll
        for (int t = 0; t < 4; ++t) {
            int row = r0 + t * 32;
            unsigned rb = (unsigned)(row * 80 + jj * 16);
            CP_ASYNC16(abuf + rb, aP[t] + kb * 32);
            CP_ASYNC16(bbuf + rb, bP[t] + kb * 32);
        }
        CP_COMMIT();
    };

    float acc[4][8][4];
    #pragma unroll
    for (int i = 0; i < 4; ++i)
        #pragma unroll
        for (int j = 0; j < 8; ++j)
            #pragma unroll
            for (int q = 0; q < 4; ++q) acc[i][j][q] = 0.f;

    issue(0, 0);
    issue(1, 1);   // KT >= 12 always

    const int a_row  = wm * 64 + (lane & 15);
    const int a_coff = (lane >> 4) * 8;
    const int b_row  = wn * 64 + (lane & 7);
    const int b_coff = ((lane >> 3) & 1) * 8;

    for (int kt = 0; kt < KT; ++kt) {
        if (kt + 1 < KT) { CP_WAIT1(); } else { CP_WAIT0(); }
        __syncthreads();
        if (kt + 2 < KT) issue((kt + 2) % 3, kt + 2);
        int cur = kt % 3;
        unsigned aoff = sbase + cur * TILE_B;
        unsigned boff = sbase + 3 * TILE_B + cur * TILE_B;
        #pragma unroll
        for (int ks = 0; ks < 2; ++ks) {
            unsigned afr[4][4], bfr[8][2];
            #pragma unroll
            for (int mf = 0; mf < 4; ++mf)
                ldsm4(afr[mf][0], afr[mf][1], afr[mf][2], afr[mf][3],
                      aoff + (unsigned)((a_row + mf * 16) * 80 + (ks * 16 + a_coff) * 2));
            #pragma unroll
            for (int nf = 0; nf < 8; ++nf)
                ldsm2(bfr[nf][0], bfr[nf][1],
                      boff + (unsigned)((b_row + nf * 8) * 80 + (ks * 16 + b_coff) * 2));
            #pragma unroll
            for (int mf = 0; mf < 4; ++mf)
                #pragma unroll
                for (int nf = 0; nf < 8; ++nf)
                    mma16816(acc[mf][nf], afr[mf], bfr[nf]);
        }
    }

    // ---- epilogue ----
    #pragma unroll
    for (int mf = 0; mf < 4; ++mf) {
        #pragma unroll
        for (int rr = 0; rr < 2; ++rr) {
            int m = bm * 128 + wm * 64 + mf * 16 + (lane >> 2) + rr * 8;
            if (MODE == 0) {
                __nv_bfloat16* dst = g_h1 + (size_t)m * CADIM + bn * 128;
                #pragma unroll
                for (int nf = 0; nf < 8; ++nf) {
                    int n = wn * 64 + nf * 8 + (lane & 3) * 2;
                    float v0 = acc[mf][nf][rr * 2 + 0] + bias[bn * 128 + n];
                    float v1 = acc[mf][nf][rr * 2 + 1] + bias[bn * 128 + n + 1];
                    __nv_bfloat162 tv = __floats2bfloat162_rn(v0, v1);
                    *reinterpret_cast<__nv_bfloat162*>(dst + n) = tv;
                }
            } else {
                int bt = m / 196, l = m - bt * 196;
                size_t base = (size_t)(bt * LTOK + 1 + l) * CDIM + bn * 128;
                #pragma unroll
                for (int nf = 0; nf < 8; ++nf) {
                    int n = wn * 64 + nf * 8 + (lane & 3) * 2;
                    float2 xv = *(const float2*)(x + base + n);
                    float2 o;
                    o.x = acc[mf][nf][rr * 2 + 0] + bias[bn * 128 + n]     + xv.x;
                    o.y = acc[mf][nf][rr * 2 + 1] + bias[bn * 128 + n + 1] + xv.y;
                    *(float2*)(out + base + n) = o;
                }
            }
        }
    }
}

// ---------------- depthwise 3x3x3 conv: 8 channels/thread ----------------
__global__ void conv_kernel(const float* __restrict__ cb) {
    int i = blockIdx.x * 256 + threadIdx.x;
    if (i >= MDIM * (CADIM / 8)) return;
    int g  = i % (CADIM / 8);
    int s  = i / (CADIM / 8);
    int ca = g * 8;
    int w  = s % NW;
    int r  = s / NW;
    int h  = r % NH; r /= NH;
    int t  = r % NT;
    int b  = r / NT;

    float acc[8];
    {
        float4 bz0 = *(const float4*)(cb + ca);
        float4 bz1 = *(const float4*)(cb + ca + 4);
        acc[0] = bz0.x; acc[1] = bz0.y; acc[2] = bz0.z; acc[3] = bz0.w;
        acc[4] = bz1.x; acc[5] = bz1.y; acc[6] = bz1.z; acc[7] = bz1.w;
    }

    #pragma unroll
    for (int dt = -1; dt <= 1; ++dt) {
        int tt = t + dt;
        if (tt < 0 || tt >= NT) continue;
        #pragma unroll
        for (int dh = -1; dh <= 1; ++dh) {
            int hh = h + dh;
            if (hh < 0 || hh >= NH) continue;
            #pragma unroll
            for (int dw = -1; dw <= 1; ++dw) {
                int ww = w + dw;
                if (ww < 0 || ww >= NW) continue;
                int j = (dt + 1) * 9 + (dh + 1) * 3 + (dw + 1);
                uint4 v = *(const uint4*)(g_h1 +
                    ((size_t)((b * NT + tt) * 196) + (hh * NW + ww)) * CADIM + ca);
                float4 w0 = *(const float4*)(g_cwT + j * CADIM + ca);
                float4 w1 = *(const float4*)(g_cwT + j * CADIM + ca + 4);
                float2 f0 = __bfloat1622float2(*reinterpret_cast<__nv_bfloat162*>(&v.x));
                float2 f1 = __bfloat1622float2(*reinterpret_cast<__nv_bfloat162*>(&v.y));
                float2 f2 = __bfloat1622float2(*reinterpret_cast<__nv_bfloat162*>(&v.z));
                float2 f3 = __bfloat1622float2(*reinterpret_cast<__nv_bfloat162*>(&v.w));
                acc[0] = fmaf(f0.x, w0.x, acc[0]);
                acc[1] = fmaf(f0.y, w0.y, acc[1]);
                acc[2] = fmaf(f1.x, w0.z, acc[2]);
                acc[3] = fmaf(f1.y, w0.w, acc[3]);
                acc[4] = fmaf(f2.x, w1.x, acc[4]);
                acc[5] = fmaf(f2.y, w1.y, acc[5]);
                acc[6] = fmaf(f3.x, w1.z, acc[6]);
                acc[7] = fmaf(f3.y, w1.w, acc[7]);
            }
        }
    }
    uint4 o;
    o.x = pack2(acc[0], acc[1]);
    o.y = pack2(acc[2], acc[3]);
    o.z = pack2(acc[4], acc[5]);
    o.w = pack2(acc[6], acc[7]);
    *(uint4*)(g_hc + (size_t)s * CADIM + ca) = o;
}

// ---------------- launch ----------------
extern "C" void kernel_launch(void* const* d_in, const int* in_sizes, int n_in,
                              void* d_out, int out_size) {
    const float* x      = (const float*)d_in[0];
    const float* W1     = (const float*)d_in[1];
    const float* b1     = (const float*)d_in[2];
    const float* conv_w = (const float*)d_in[3];
    const float* conv_b = (const float*)d_in[4];
    const float* W2     = (const float*)d_in[5];
    const float* b2     = (const float*)d_in[6];
    float* out = (float*)d_out;

    cudaFuncSetAttribute(gemm_mma<0>, cudaFuncAttributeMaxDynamicSharedMemorySize, SMEM_SZ);
    cudaFuncSetAttribute(gemm_mma<1>, cudaFuncAttributeMaxDynamicSharedMemorySize, SMEM_SZ);

    convert_weights<<<(CADIM * CDIM + 255) / 256, 256>>>(W1, W2, conv_w);
    convert_x_cls<<<(MDIM * (CDIM / 8) + 255) / 256, 256>>>(x, out);
    gemm_mma<0><<<dim3(CADIM / 128, MDIM / 128), 128, SMEM_SZ>>>(x, b1, nullptr);
    conv_kernel<<<(MDIM * (CADIM / 8) + 255) / 256, 256>>>(conv_b);
    gemm_mma<1><<<dim3(CDIM / 128, MDIM / 128), 128, SMEM_SZ>>>(x, b2, out);
}

// round 17
// speedup vs baseline: 2.1193x; 1.1447x over previous
#include <cuda_runtime.h>
#include <cuda_bf16.h>
#include <cstdint>

#define BT    256
#define LTOK  197
#define CDIM  768
#define CADIM 384
#define NT    8
#define NH    14
#define NW    14
#define MDIM  (BT*196)   /* 50176 */

// ---------------- scratch ----------------
__device__ __align__(256) __nv_bfloat16 g_xb[(size_t)MDIM * CDIM];    // x bf16, CLS removed
__device__ __align__(256) __nv_bfloat16 g_h1[(size_t)MDIM * CADIM];
__device__ __align__(256) __nv_bfloat16 g_hc[(size_t)MDIM * CADIM];
__device__ __align__(256) __nv_bfloat16 g_w1b[CADIM * CDIM];
__device__ __align__(256) __nv_bfloat16 g_w2b[CDIM * CADIM];
__device__ __align__(256) float         g_cwT[27 * CADIM];

// ---------------- helpers ----------------
__device__ __forceinline__ unsigned sm32(const void* p) {
    unsigned a;
    asm("{.reg .u64 t; cvta.to.shared.u64 t, %1; cvt.u32.u64 %0, t;}" : "=r"(a) : "l"(p));
    return a;
}
__device__ __forceinline__ unsigned pack2(float a, float b) {
    __nv_bfloat162 t = __floats2bfloat162_rn(a, b);
    return *reinterpret_cast<unsigned*>(&t);
}
__device__ __forceinline__ void ldsm4(unsigned& r0, unsigned& r1, unsigned& r2, unsigned& r3, unsigned addr) {
    asm volatile("ldmatrix.sync.aligned.m8n8.x4.shared.b16 {%0,%1,%2,%3}, [%4];\n"
                 : "=r"(r0), "=r"(r1), "=r"(r2), "=r"(r3) : "r"(addr));
}
__device__ __forceinline__ void ldsm2(unsigned& r0, unsigned& r1, unsigned addr) {
    asm volatile("ldmatrix.sync.aligned.m8n8.x2.shared.b16 {%0,%1}, [%2];\n"
                 : "=r"(r0), "=r"(r1) : "r"(addr));
}
__device__ __forceinline__ void mma16816(float* c, const unsigned* a, const unsigned* b) {
    asm volatile(
        "mma.sync.aligned.m16n8k16.row.col.f32.bf16.bf16.f32 "
        "{%0,%1,%2,%3}, {%4,%5,%6,%7}, {%8,%9}, {%0,%1,%2,%3};\n"
        : "+f"(c[0]), "+f"(c[1]), "+f"(c[2]), "+f"(c[3])
        : "r"(a[0]), "r"(a[1]), "r"(a[2]), "r"(a[3]), "r"(b[0]), "r"(b[1]));
}

#define CP_ASYNC16(sa, ga) \
    asm volatile("cp.async.cg.shared.global [%0], [%1], 16;" :: "r"(sa), "l"(ga) : "memory")
#define CP_COMMIT() asm volatile("cp.async.commit_group;" ::: "memory")
#define CP_WAIT1()  asm volatile("cp.async.wait_group 1;" ::: "memory")
#define CP_WAIT0()  asm volatile("cp.async.wait_group 0;" ::: "memory")

// ---------------- weight conversion ----------------
__global__ void convert_weights(const float* __restrict__ W1, const float* __restrict__ W2,
                                const float* __restrict__ cw) {
    int i = blockIdx.x * 256 + threadIdx.x;
    if (i < CADIM * CDIM) {
        g_w1b[i] = __float2bfloat16(W1[i]);
        g_w2b[i] = __float2bfloat16(W2[i]);
    }
    if (i < 27 * CADIM) {
        int j = i / CADIM, ca = i % CADIM;
        g_cwT[i] = cw[ca * 27 + j];
    }
}

// ---------------- x fp32 -> bf16 compact (CLS removed) + CLS passthrough ----------------
__global__ void convert_x_cls(const float* __restrict__ x, float* __restrict__ out) {
    int i = blockIdx.x * 256 + threadIdx.x;
    if (i < MDIM * (CDIM / 8)) {
        int m = i / (CDIM / 8);
        int part = i - m * (CDIM / 8);
        int bt = m / 196, l = m - bt * 196;
        const float* src = x + (size_t)(bt * LTOK + 1 + l) * CDIM + part * 8;
        float4 v0 = *(const float4*)src;
        float4 v1 = *(const float4*)(src + 4);
        uint4 o = make_uint4(pack2(v0.x, v0.y), pack2(v0.z, v0.w),
                             pack2(v1.x, v1.y), pack2(v1.z, v1.w));
        *(uint4*)(g_xb + (size_t)m * CDIM + part * 8) = o;
    }
    if (i < BT * (CDIM / 4)) {
        int bt = i / (CDIM / 4);
        int c  = (i - bt * (CDIM / 4)) * 4;
        size_t off = (size_t)bt * LTOK * CDIM + c;
        *(float4*)(out + off) = *(const float4*)(x + off);
    }
}

// ---------------- GEMM: mma.sync bf16, CTA 128x128, 4 warps @ 64x64, 3-stage cp.async ----
#define TILE_B  10240
#define SMEM_SZ (6 * TILE_B)

template <int MODE>
__global__ __launch_bounds__(128, 2) void gemm_mma(
    const float* __restrict__ x, const float* __restrict__ bias, float* __restrict__ out)
{
    constexpr int K  = (MODE == 0) ? CDIM : CADIM;
    constexpr int KT = K / 32;

    extern __shared__ char smem[];
    const unsigned sbase = sm32(smem);

    const int tid  = threadIdx.x;
    const int warp = tid >> 5, lane = tid & 31;
    const int wm = warp >> 1, wn = warp & 1;
    const int bn = blockIdx.x, bm = blockIdx.y;

    const __nv_bfloat16* Asrc = (MODE == 0) ? g_xb : g_hc;
    const __nv_bfloat16* Bw   = (MODE == 0) ? g_w1b : g_w2b;

    const int jj = tid & 3;
    const int r0 = tid >> 2;

    const __nv_bfloat16* aP[4];
    const __nv_bfloat16* bP[4];
    #pragma unroll
    for (int t = 0; t < 4; ++t) {
        int row = r0 + t * 32;
        aP[t] = Asrc + (size_t)(bm * 128 + row) * K + jj * 8;
        bP[t] = Bw   + (size_t)(bn * 128 + row) * K + jj * 8;
    }

    auto issue = [&](int buf, int kb) {
        unsigned abuf = sbase + buf * TILE_B;
        unsigned bbuf = sbase + 3 * TILE_B + buf * TILE_B;
        #pragma unroll
        for (int t = 0; t < 4; ++t) {
            int row = r0 + t * 32;
            unsigned rb = (unsigned)(row * 80 + jj * 16);
            CP_ASYNC16(abuf + rb, aP[t] + kb * 32);
            CP_ASYNC16(bbuf + rb, bP[t] + kb * 32);
        }
        CP_COMMIT();
    };

    float acc[4][8][4];
    #pragma unroll
    for (int i = 0; i < 4; ++i)
        #pragma unroll
        for (int j = 0; j < 8; ++j)
            #pragma unroll
            for (int q = 0; q < 4; ++q) acc[i][j][q] = 0.f;

    issue(0, 0);
    issue(1, 1);

    const int a_row  = wm * 64 + (lane & 15);
    const int a_coff = (lane >> 4) * 8;
    const int b_row  = wn * 64 + (lane & 7);
    const int b_coff = ((lane >> 3) & 1) * 8;

    for (int kt = 0; kt < KT; ++kt) {
        if (kt + 1 < KT) { CP_WAIT1(); } else { CP_WAIT0(); }
        __syncthreads();
        if (kt + 2 < KT) issue((kt + 2) % 3, kt + 2);
        int cur = kt % 3;
        unsigned aoff = sbase + cur * TILE_B;
        unsigned boff = sbase + 3 * TILE_B + cur * TILE_B;
        #pragma unroll
        for (int ks = 0; ks < 2; ++ks) {
            unsigned afr[4][4], bfr[8][2];
            #pragma unroll
            for (int mf = 0; mf < 4; ++mf)
                ldsm4(afr[mf][0], afr[mf][1], afr[mf][2], afr[mf][3],
                      aoff + (unsigned)((a_row + mf * 16) * 80 + (ks * 16 + a_coff) * 2));
            #pragma unroll
            for (int nf = 0; nf < 8; ++nf)
                ldsm2(bfr[nf][0], bfr[nf][1],
                      boff + (unsigned)((b_row + nf * 8) * 80 + (ks * 16 + b_coff) * 2));
            #pragma unroll
            for (int mf = 0; mf < 4; ++mf)
                #pragma unroll
                for (int nf = 0; nf < 8; ++nf)
                    mma16816(acc[mf][nf], afr[mf], bfr[nf]);
        }
    }

    #pragma unroll
    for (int mf = 0; mf < 4; ++mf) {
        #pragma unroll
        for (int rr = 0; rr < 2; ++rr) {
            int m = bm * 128 + wm * 64 + mf * 16 + (lane >> 2) + rr * 8;
            if (MODE == 0) {
                __nv_bfloat16* dst = g_h1 + (size_t)m * CADIM + bn * 128;
                #pragma unroll
                for (int nf = 0; nf < 8; ++nf) {
                    int n = wn * 64 + nf * 8 + (lane & 3) * 2;
                    float v0 = acc[mf][nf][rr * 2 + 0] + bias[bn * 128 + n];
                    float v1 = acc[mf][nf][rr * 2 + 1] + bias[bn * 128 + n + 1];
                    __nv_bfloat162 tv = __floats2bfloat162_rn(v0, v1);
                    *reinterpret_cast<__nv_bfloat162*>(dst + n) = tv;
                }
            } else {
                int bt = m / 196, l = m - bt * 196;
                size_t base = (size_t)(bt * LTOK + 1 + l) * CDIM + bn * 128;
                #pragma unroll
                for (int nf = 0; nf < 8; ++nf) {
                    int n = wn * 64 + nf * 8 + (lane & 3) * 2;
                    float2 xv = *(const float2*)(x + base + n);
                    float2 o;
                    o.x = acc[mf][nf][rr * 2 + 0] + bias[bn * 128 + n]     + xv.x;
                    o.y = acc[mf][nf][rr * 2 + 1] + bias[bn * 128 + n + 1] + xv.y;
                    *(float2*)(out + base + n) = o;
                }
            }
        }
    }
}

// ---------------- depthwise 3x3x3 conv: 7 outputs (half w-row) x 8 channels per thread ----
// Thread i -> (g, half, row): i = (row*2 + half)*48 + g ; row = bt*14 + h
#define CONV_THREADS (256 * 14 * 2 * (CADIM / 8))   /* 344064 */

__global__ __launch_bounds__(128) void conv_kernel(const float* __restrict__ cb) {
    int i = blockIdx.x * 128 + threadIdx.x;
    if (i >= CONV_THREADS) return;
    int g    = i % (CADIM / 8);
    int rh   = i / (CADIM / 8);
    int half = rh & 1;
    int row  = rh >> 1;
    int h    = row % 14;
    int bt   = row / 14;       // 0..255
    int t    = bt & 7;
    int ca   = g * 8;
    int wbase = half * 7;

    float acc[7][8];
    {
        float4 bz0 = *(const float4*)(cb + ca);
        float4 bz1 = *(const float4*)(cb + ca + 4);
        #pragma unroll
        for (int p = 0; p < 7; ++p) {
            acc[p][0] = bz0.x; acc[p][1] = bz0.y; acc[p][2] = bz0.z; acc[p][3] = bz0.w;
            acc[p][4] = bz1.x; acc[p][5] = bz1.y; acc[p][6] = bz1.z; acc[p][7] = bz1.w;
        }
    }

    for (int dt = -1; dt <= 1; ++dt) {
        int tt = t + dt;
        if (tt < 0 || tt >= NT) continue;
        for (int dh = -1; dh <= 1; ++dh) {
            int hh = h + dh;
            if (hh < 0 || hh >= NH) continue;
            const __nv_bfloat16* base =
                g_h1 + ((size_t)(bt + dt) * 196 + hh * NW) * CADIM + ca;
            // stage 9 input vectors covering w = wbase-1 .. wbase+7
            uint4 vin[9];
            #pragma unroll
            for (int q = 0; q < 9; ++q) {
                int wq = wbase - 1 + q;
                if (wq >= 0 && wq < NW)
                    vin[q] = *(const uint4*)(base + (size_t)wq * CADIM);
                else
                    vin[q] = make_uint4(0, 0, 0, 0);
            }
            int jrow = (dt + 1) * 9 + (dh + 1) * 3;
            #pragma unroll
            for (int dw = 0; dw < 3; ++dw) {
                const float* wt = g_cwT + (jrow + dw) * CADIM + ca;
                float4 w0 = *(const float4*)wt;
                float4 w1 = *(const float4*)(wt + 4);
                #pragma unroll
                for (int p = 0; p < 7; ++p) {
                    uint4 v = vin[p + dw];
                    float2 f0 = __bfloat1622float2(*reinterpret_cast<__nv_bfloat162*>(&v.x));
                    float2 f1 = __bfloat1622float2(*reinterpret_cast<__nv_bfloat162*>(&v.y));
                    float2 f2 = __bfloat1622float2(*reinterpret_cast<__nv_bfloat162*>(&v.z));
                    float2 f3 = __bfloat1622float2(*reinterpret_cast<__nv_bfloat162*>(&v.w));
                    acc[p][0] = fmaf(f0.x, w0.x, acc[p][0]);
                    acc[p][1] = fmaf(f0.y, w0.y, acc[p][1]);
                    acc[p][2] = fmaf(f1.x, w0.z, acc[p][2]);
                    acc[p][3] = fmaf(f1.y, w0.w, acc[p][3]);
                    acc[p][4] = fmaf(f2.x, w1.x, acc[p][4]);
                    acc[p][5] = fmaf(f2.y, w1.y, acc[p][5]);
                    acc[p][6] = fmaf(f3.x, w1.z, acc[p][6]);
                    acc[p][7] = fmaf(f3.y, w1.w, acc[p][7]);
                }
            }
        }
    }

    __nv_bfloat16* dst = g_hc + ((size_t)bt * 196 + h * NW + wbase) * CADIM + ca;
    #pragma unroll
    for (int p = 0; p < 7; ++p) {
        uint4 o;
        o.x = pack2(acc[p][0], acc[p][1]);
        o.y = pack2(acc[p][2], acc[p][3]);
        o.z = pack2(acc[p][4], acc[p][5]);
        o.w = pack2(acc[p][6], acc[p][7]);
        *(uint4*)(dst + (size_t)p * CADIM) = o;
    }
}

// ---------------- launch ----------------
extern "C" void kernel_launch(void* const* d_in, const int* in_sizes, int n_in,
                              void* d_out, int out_size) {
    const float* x      = (const float*)d_in[0];
    const float* W1     = (const float*)d_in[1];
    const float* b1     = (const float*)d_in[2];
    const float* conv_w = (const float*)d_in[3];
    const float* conv_b = (const float*)d_in[4];
    const float* W2     = (const float*)d_in[5];
    const float* b2     = (const float*)d_in[6];
    float* out = (float*)d_out;

    cudaFuncSetAttribute(gemm_mma<0>, cudaFuncAttributeMaxDynamicSharedMemorySize, SMEM_SZ);
    cudaFuncSetAttribute(gemm_mma<1>, cudaFuncAttributeMaxDynamicSharedMemorySize, SMEM_SZ);

    convert_weights<<<(CADIM * CDIM + 255) / 256, 256>>>(W1, W2, conv_w);
    convert_x_cls<<<(MDIM * (CDIM / 8) + 255) / 256, 256>>>(x, out);
    gemm_mma<0><<<dim3(CADIM / 128, MDIM / 128), 128, SMEM_SZ>>>(x, b1, nullptr);
    conv_kernel<<<(CONV_THREADS + 127) / 128, 128>>>(conv_b);
    gemm_mma<1><<<dim3(CDIM / 128, MDIM / 128), 128, SMEM_SZ>>>(x, b2, out);
}